// round 5
// baseline (speedup 1.0000x reference)
#include <cuda_runtime.h>

// NLL: out = -mean(log(x[i, y[i]])), x: [N=8192, C=32000] f32.
// y is nominally int64 in the reference, but JAX without x64 silently emits
// int32 — sniff the layout at runtime (odd 32-bit words all zero <=> int64).
// Single fused kernel: per-block partials + wrap-around counter, last block
// reduces in fixed order (bit-deterministic, graph-replay safe).

#define N_ROWS   8192
#define N_COLS   32000
#define BLOCKS   64
#define THREADS  128

__device__ float        g_partials[BLOCKS];
__device__ unsigned int g_done_count = 0;   // atomicInc wraps to 0 each launch

__global__ void __launch_bounds__(THREADS) nll_kernel(
    const float* __restrict__ x,
    const int*   __restrict__ y32,   // raw view of the label buffer
    float* __restrict__ out)
{
    const int row  = blockIdx.x * THREADS + threadIdx.x;   // 64*128 == 8192 exactly
    const int lane = threadIdx.x & 31;
    const int wid  = threadIdx.x >> 5;

    // --- dtype sniff (touches only the first 32 bytes; safe in either layout) ---
    // int64 little-endian labels < 2^31  => words 1,3,5,7 are zero high-words.
    // int32 labels in [0,32000)          => all-four-zero is ~impossible.
    const bool is_i64 = ((y32[1] | y32[3] | y32[5] | y32[7]) == 0);

    long long col = is_i64 ? ((const long long*)y32)[row]
                           : (long long)y32[row];
    // Defensive clamp: a wrong sniff becomes a rel_err failure, never an IMA.
    if (col < 0) col = 0;
    if (col >= N_COLS) col = N_COLS - 1;

    const float p = x[(long long)row * N_COLS + col];
    float v = -__logf(p);

    // Warp reduce
    #pragma unroll
    for (int off = 16; off > 0; off >>= 1)
        v += __shfl_xor_sync(0xFFFFFFFFu, v, off);

    // Block reduce across 4 warps
    __shared__ float s_warp[THREADS / 32];
    __shared__ bool  s_is_last;
    if (lane == 0) s_warp[wid] = v;
    __syncthreads();

    if (threadIdx.x == 0) {
        const float b = s_warp[0] + s_warp[1] + s_warp[2] + s_warp[3];
        g_partials[blockIdx.x] = b;
        __threadfence();  // publish partial before signaling
        const unsigned int old = atomicInc(&g_done_count, BLOCKS - 1);  // wraps -> replay safe
        s_is_last = (old == BLOCKS - 1);
    }
    __syncthreads();

    // Last-arriving block reduces all 64 partials in fixed order (deterministic).
    if (s_is_last && wid == 0) {
        __threadfence();  // see all partials
        float a = g_partials[lane] + g_partials[lane + 32];
        #pragma unroll
        for (int off = 16; off > 0; off >>= 1)
            a += __shfl_xor_sync(0xFFFFFFFFu, a, off);
        if (lane == 0)
            out[0] = a * (1.0f / (float)N_ROWS);
    }
}

extern "C" void kernel_launch(void* const* d_in, const int* in_sizes, int n_in,
                              void* d_out, int out_size)
{
    const float* x   = (const float*)d_in[0];
    const int*   y   = (const int*)d_in[1];
    float*       out = (float*)d_out;

    nll_kernel<<<BLOCKS, THREADS>>>(x, y, out);
}

// round 11
// speedup vs baseline: 1.2546x; 1.2546x over previous
#include <cuda_runtime.h>

// NLL: out = -mean(log(x[i, y[i]])), x: [N=8192, C=32000] f32, y int32[N].
// (y proven int32: Round-2 pure-int64 read IMA'd; Round-5 sniff passed.)
// Latency-bound => minimize the serial chain:
//   LDG y (coalesced) -> LDG x (scattered 4B gather) -> warp+block reduce
//   -> ONE fused 64-bit atomicAdd (fixed-point sum in low 56 bits, arrival
//      ticket at bit 56). 64th arriver finalizes and resets the accumulator
//      (graph-replay safe). Integer adds commute -> bit-deterministic.

#define N_ROWS   8192
#define N_COLS   32000
#define BLOCKS   64
#define THREADS  128

#define TICKET   (1ULL << 56)
#define SUM_MASK (TICKET - 1ULL)
#define FP_SCALE 4294967296.0      // 2^32

__device__ unsigned long long g_acc = 0;   // reset by last block each launch

__global__ void __launch_bounds__(THREADS) nll_kernel(
    const float* __restrict__ x,
    const int*   __restrict__ y,
    float* __restrict__ out)
{
    const int row  = blockIdx.x * THREADS + threadIdx.x;   // 64*128 == 8192 exactly
    const int lane = threadIdx.x & 31;
    const int wid  = threadIdx.x >> 5;

    // Coalesced int32 label load; clamp => any dtype surprise becomes a
    // rel_err failure, never an IMA.
    int col = y[row];
    col = (col < 0) ? 0 : (col >= N_COLS ? N_COLS - 1 : col);

    // 32-bit indexing: max index 8191*32000+31999 < 2^31 (byte offset too).
    const float p = x[row * N_COLS + col];
    float v = -__logf(p);          // p in (1e-6, 1) => v in (0, ~13.9), >= 0

    // Warp reduce (fixed order)
    #pragma unroll
    for (int off = 16; off > 0; off >>= 1)
        v += __shfl_xor_sync(0xFFFFFFFFu, v, off);

    __shared__ float s_warp[THREADS / 32];
    if (lane == 0) s_warp[wid] = v;
    __syncthreads();

    // Scalar tail: one thread per block, one atomic total.
    if (threadIdx.x == 0) {
        const double b = (double)s_warp[0] + (double)s_warp[1]
                       + (double)s_warp[2] + (double)s_warp[3];
        // Fixed-point quantize: q <= 1769*2^32 < 2^43; 64 blocks < 2^49 < 2^56.
        const unsigned long long q =
            (unsigned long long)(b * FP_SCALE + 0.5);

        const unsigned long long old = atomicAdd(&g_acc, q + TICKET);

        if ((old >> 56) == (BLOCKS - 1)) {            // 64th (last) arrival
            const unsigned long long total = (old & SUM_MASK) + q;
            out[0] = (float)((double)total * (1.0 / FP_SCALE)
                             * (1.0 / (double)N_ROWS));
            g_acc = 0;                                // reset for next replay
        }
    }
}

extern "C" void kernel_launch(void* const* d_in, const int* in_sizes, int n_in,
                              void* d_out, int out_size)
{
    const float* x   = (const float*)d_in[0];
    const int*   yin = (const int*)d_in[1];
    float*       out = (float*)d_out;

    nll_kernel<<<BLOCKS, THREADS>>>(x, yin, out);
}